// round 17
// baseline (speedup 1.0000x reference)
#include <cuda_runtime.h>
#include <cuda_fp16.h>
#include <cstdint>

// Problem constants
#define NS 131072
#define DD 16
#define RR 32
#define OO 10
#define EPSV 1e-8f

#define TPB 512
#define SPC 256            // samples per CTA (16 warps x 16)
#define GRID (NS / SPC)    // 512

// ---- prebuilt fragment tables (prep_kernel output) ----
// Affine B (fp16 hi), nt-pairs: [ntp*32 + lane] -> (nt0.b0, nt0.b1, nt1.b0, nt1.b1)
__device__ __align__(16) uint4  gBF[640];
// Affine bias (fp32), nt-pairs: [ntp*4 + t] -> (nt0.n0, nt0.n1, nt1.n0, nt1.n1)
__device__ __align__(16) float4 gBias[80];
// Strength B (fp16 hi+lo): [(nt*2+kt)*32 + lane] -> (hi.b0, hi.b1, lo.b0, lo.b1)
__device__ __align__(16) uint4  gGF[256];
// Strength const (exact fp32): [nt*4 + t] -> (const_r0, const_r1)
__device__ __align__(16) float2 gConst[16];

// ---------------- helpers ----------------
__device__ __forceinline__ uint32_t h2pk(float a, float b) {
    __half2 h = __floats2half2_rn(a, b);
    return *reinterpret_cast<uint32_t*>(&h);
}
__device__ __forceinline__ float hround(float v) {
    return __half2float(__float2half_rn(v));
}

// m16n8k16 fp16 mma, f32 accumulate (sm_80 PTX path, valid on plain sm_100)
__device__ __forceinline__ void mma_f16(float c[4], const uint32_t a[4],
                                        uint32_t b0, uint32_t b1) {
    asm volatile(
        "mma.sync.aligned.m16n8k16.row.col.f32.f16.f16.f32 "
        "{%0,%1,%2,%3}, {%4,%5,%6,%7}, {%8,%9}, {%0,%1,%2,%3};"
        : "+f"(c[0]), "+f"(c[1]), "+f"(c[2]), "+f"(c[3])
        : "r"(a[0]), "r"(a[1]), "r"(a[2]), "r"(a[3]), "r"(b0), "r"(b1));
}

// strength B element G[k][r]: k<16 -> x^2 coeff (-1/2s^2); [16,32) -> x coeff (c/s^2)
__device__ float gval(const float* __restrict__ centers,
                      const float* __restrict__ sigmas, int r, int k) {
    if (k < 16) {
        float sg = sigmas[r * 16 + k];
        return -0.5f / (sg * sg);
    }
    int d = k - 16;
    float sg = sigmas[r * 16 + d];
    return centers[r * 16 + d] / (sg * sg);
}

__global__ void prep_kernel(const float* __restrict__ centers,
                            const float* __restrict__ sigmas,
                            const float* __restrict__ coeffs) {
    int i = blockIdx.x * blockDim.x + threadIdx.x;

    // strength B fragments (fp16 hi+lo)
    if (i < 256) {
        int l = i & 31, kt = (i >> 5) & 1, nt = i >> 6;
        int t = l & 3, g = l >> 2;
        int r = nt * 8 + g;
        int kb = kt * 16;
        float v0 = gval(centers, sigmas, r, kb + 2 * t);
        float v1 = gval(centers, sigmas, r, kb + 2 * t + 1);
        float v8 = gval(centers, sigmas, r, kb + 2 * t + 8);
        float v9 = gval(centers, sigmas, r, kb + 2 * t + 9);
        uint4 w;
        w.x = h2pk(v0, v1);
        w.y = h2pk(v8, v9);
        w.z = h2pk(v0 - hround(v0), v1 - hround(v1));
        w.w = h2pk(v8 - hround(v8), v9 - hround(v9));
        gGF[i] = w;
    }
    // affine B fragments, nt-pairs
    int j = i - 256;
    if (j >= 0 && j < 640) {
        int l = j & 31, ntp = j >> 5;
        int t = l & 3, g = l >> 2;
        int k = 2 * t;
        int na = ntp * 16 + g;       // nt0 = 2*ntp
        int nb = na + 8;             // nt1 = 2*ntp+1
        int oa = na >> 5, ra = na & 31;
        int ob = nb >> 5, rb = nb & 31;
        uint4 w;
        w.x = h2pk(coeffs[(ra * 17 + k) * 10 + oa], coeffs[(ra * 17 + k + 1) * 10 + oa]);
        w.y = h2pk(coeffs[(ra * 17 + k + 8) * 10 + oa], coeffs[(ra * 17 + k + 9) * 10 + oa]);
        w.z = h2pk(coeffs[(rb * 17 + k) * 10 + ob], coeffs[(rb * 17 + k + 1) * 10 + ob]);
        w.w = h2pk(coeffs[(rb * 17 + k + 8) * 10 + ob], coeffs[(rb * 17 + k + 9) * 10 + ob]);
        gBF[j] = w;
    }
    // affine bias, nt-pairs (exact fp32)
    int b = i - 896;
    if (b >= 0 && b < 80) {
        int ntp = b >> 2, t = b & 3;
        int n0 = ntp * 16 + 2 * t;       // nt0 rows
        int n2 = n0 + 8;                 // nt1 rows
        float4 w;
        w.x = coeffs[((n0 & 31) * 17 + 16) * 10 + (n0 >> 5)];
        w.y = coeffs[(((n0 + 1) & 31) * 17 + 16) * 10 + ((n0 + 1) >> 5)];
        w.z = coeffs[((n2 & 31) * 17 + 16) * 10 + (n2 >> 5)];
        w.w = coeffs[(((n2 + 1) & 31) * 17 + 16) * 10 + ((n2 + 1) >> 5)];
        gBias[b] = w;
    }
    // strength const pairs (exact fp32)
    int q = i - 976;
    if (q >= 0 && q < 16) {
        int nt = q >> 2, t = q & 3;
        int r0 = nt * 8 + 2 * t;
        float acc0 = 0.0f, acc1 = 0.0f;
        for (int d = 0; d < 16; d++) {
            float c0 = centers[r0 * 16 + d], s0 = sigmas[r0 * 16 + d];
            float c1 = centers[(r0 + 1) * 16 + d], s1 = sigmas[(r0 + 1) * 16 + d];
            acc0 += -0.5f * c0 * c0 / (s0 * s0);
            acc1 += -0.5f * c1 * c1 / (s1 * s1);
        }
        float2 w; w.x = acc0; w.y = acc1;
        gConst[q] = w;
    }
}

__device__ __forceinline__ void finish_sample(const float v_in[10], float ssum,
                                              float* __restrict__ outp) {
    float v[10];
    float inv = __fdividef(1.0f, ssum + EPSV);
    #pragma unroll
    for (int i = 0; i < 10; i++) v[i] = v_in[i] * inv;
    float m = v[0];
    #pragma unroll
    for (int i = 1; i < 10; i++) m = fmaxf(m, v[i]);
    float se = 0.0f;
    #pragma unroll
    for (int i = 0; i < 10; i++) { v[i] = __expf(v[i] - m); se += v[i]; }
    float is = __fdividef(1.0f, se);
    float2* o2 = (float2*)outp;  // row base 40B -> 8B aligned
    #pragma unroll
    for (int j = 0; j < 5; j++) {
        float2 w; w.x = v[2 * j] * is; w.y = v[2 * j + 1] * is;
        o2[j] = w;
    }
}

__global__ void __launch_bounds__(TPB, 2)
anfis_kernel(const float* __restrict__ X, float* __restrict__ out) {
    __shared__ __align__(16) float  smX[SPC * 24];   // 24 KB
    __shared__ __align__(16) uint4  sBF[640];        // 10 KB
    __shared__ __align__(16) float4 sBias[80];       // 1.25 KB
    __shared__ __align__(16) uint4  sGF[256];        // 4 KB
    __shared__ __align__(16) float2 sConst[16];      // 128 B

    const int tid = threadIdx.x;
    const int lane = tid & 31;
    const int warp = tid >> 5;   // 0..15
    const int g = lane >> 2;     // group (row within tile)
    const int t = lane & 3;      // thread-in-group

    // ---- stage X (256 rows x 16, stride 24) + copy fragment tables ----
    {
        const float4* Xv = (const float4*)(X + (size_t)blockIdx.x * SPC * DD);
        #pragma unroll
        for (int it = 0; it < 2; it++) {
            int i = tid + it * TPB;
            int row = i >> 2, q = i & 3;
            *(float4*)(smX + row * 24 + q * 4) = Xv[i];
        }
        // sBF has 640 entries; TPB=512 -> every thread copies one, first 128
        // copy a second (the R16 bug: an unreachable else left 512..639 garbage)
        sBF[tid] = __ldg(&gBF[tid]);
        if (tid < 128) sBF[512 + tid] = __ldg(&gBF[512 + tid]);
        if (tid >= 128 && tid < 384) sGF[tid - 128] = __ldg(&gGF[tid - 128]);
        if (tid >= 384 && tid < 464) sBias[tid - 384] = __ldg(&gBias[tid - 384]);
        if (tid >= 464 && tid < 472)
            ((float4*)sConst)[tid - 464] = __ldg(&((const float4*)gConst)[tid - 464]);
    }
    __syncthreads();

    // ---- A fragments for rows ws+g, ws+g+8 (fp16 hi/lo for x and x^2) ----
    const int ws = warp * 16;
    uint32_t xh[4], xl[4], sqh[4], sql[4];
    {
        const float* x0 = smX + (ws + g) * 24;
        const float* x1 = smX + (ws + g + 8) * 24;
        float2 p0 = *(const float2*)(x0 + 2 * t);
        float2 p0c = *(const float2*)(x0 + 2 * t + 8);
        float2 p1 = *(const float2*)(x1 + 2 * t);
        float2 p1c = *(const float2*)(x1 + 2 * t + 8);

        xh[0] = h2pk(p0.x, p0.y);
        xh[1] = h2pk(p1.x, p1.y);
        xh[2] = h2pk(p0c.x, p0c.y);
        xh[3] = h2pk(p1c.x, p1c.y);
        xl[0] = h2pk(p0.x - hround(p0.x), p0.y - hround(p0.y));
        xl[1] = h2pk(p1.x - hround(p1.x), p1.y - hround(p1.y));
        xl[2] = h2pk(p0c.x - hround(p0c.x), p0c.y - hround(p0c.y));
        xl[3] = h2pk(p1c.x - hround(p1c.x), p1c.y - hround(p1c.y));

        float q0x = p0.x * p0.x, q0y = p0.y * p0.y;
        float q1x = p1.x * p1.x, q1y = p1.y * p1.y;
        float q0cx = p0c.x * p0c.x, q0cy = p0c.y * p0c.y;
        float q1cx = p1c.x * p1c.x, q1cy = p1c.y * p1c.y;
        sqh[0] = h2pk(q0x, q0y);
        sqh[1] = h2pk(q1x, q1y);
        sqh[2] = h2pk(q0cx, q0cy);
        sqh[3] = h2pk(q1cx, q1cy);
        sql[0] = h2pk(q0x - hround(q0x), q0y - hround(q0y));
        sql[1] = h2pk(q1x - hround(q1x), q1y - hround(q1y));
        sql[2] = h2pk(q0cx - hround(q0cx), q0cy - hround(q0cy));
        sql[3] = h2pk(q1cx - hround(q1cx), q1cy - hround(q1cy));
    }

    // ---- strength GEMM: e = [x^2 | x] . G + const; 3 comp chains per nt ----
    float s0[8], s1[8];
    float ssum0 = 0.0f, ssum1 = 0.0f;
    #pragma unroll
    for (int nt = 0; nt < 4; nt++) {
        float2 cst = sConst[nt * 4 + t];
        float ch[4] = {cst.x, cst.y, cst.x, cst.y};
        float cla[4] = {0.f, 0.f, 0.f, 0.f};
        float clb[4] = {0.f, 0.f, 0.f, 0.f};
        #pragma unroll
        for (int kt = 0; kt < 2; kt++) {
            uint4 gq = sGF[(nt * 2 + kt) * 32 + lane];
            const uint32_t* Ah = (kt == 0) ? sqh : xh;
            const uint32_t* Al = (kt == 0) ? sql : xl;
            mma_f16(ch, Ah, gq.x, gq.y);
            mma_f16(cla, Ah, gq.z, gq.w);
            mma_f16(clb, Al, gq.x, gq.y);
        }
        s0[nt * 2] = __expf(ch[0] + cla[0] + clb[0]);
        s0[nt * 2 + 1] = __expf(ch[1] + cla[1] + clb[1]);
        s1[nt * 2] = __expf(ch[2] + cla[2] + clb[2]);
        s1[nt * 2 + 1] = __expf(ch[3] + cla[3] + clb[3]);
        ssum0 += s0[nt * 2] + s0[nt * 2 + 1];
        ssum1 += s1[nt * 2] + s1[nt * 2 + 1];
    }

    // ---- affine GEMM: nt-pairs, 2 MMAs per iteration, bias in acc init ----
    float out0[10], out1[10];
    #pragma unroll
    for (int i = 0; i < 10; i++) { out0[i] = 0.0f; out1[i] = 0.0f; }
    #pragma unroll
    for (int ntp = 0; ntp < 20; ntp++) {
        uint4 bq = sBF[ntp * 32 + lane];
        float4 bs = sBias[ntp * 4 + t];
        // nt0 = 2*ntp
        {
            float c[4] = {bs.x, bs.y, bs.x, bs.y};
            mma_f16(c, xh, bq.x, bq.y);
            const int nt = 2 * ntp;
            const int o = nt >> 2;
            const int j2 = (nt & 3) * 2;
            out0[o] += s0[j2] * c[0] + s0[j2 + 1] * c[1];
            out1[o] += s1[j2] * c[2] + s1[j2 + 1] * c[3];
        }
        // nt1 = 2*ntp+1
        {
            float c[4] = {bs.z, bs.w, bs.z, bs.w};
            mma_f16(c, xh, bq.z, bq.w);
            const int nt = 2 * ntp + 1;
            const int o = nt >> 2;
            const int j2 = (nt & 3) * 2;
            out0[o] += s0[j2] * c[0] + s0[j2 + 1] * c[1];
            out1[o] += s1[j2] * c[2] + s1[j2 + 1] * c[3];
        }
    }

    // ---- reduce across the 4 lanes of each group (t dimension) ----
    #pragma unroll
    for (int m = 1; m <= 2; m <<= 1) {
        #pragma unroll
        for (int i = 0; i < 10; i++) {
            out0[i] += __shfl_xor_sync(0xffffffffu, out0[i], m);
            out1[i] += __shfl_xor_sync(0xffffffffu, out1[i], m);
        }
        ssum0 += __shfl_xor_sync(0xffffffffu, ssum0, m);
        ssum1 += __shfl_xor_sync(0xffffffffu, ssum1, m);
    }

    // ---- finalize (t==0 lanes own rows ws+g and ws+g+8) ----
    if (t == 0) {
        const size_t base = (size_t)blockIdx.x * SPC;
        finish_sample(out0, ssum0, out + (base + ws + g) * OO);
        finish_sample(out1, ssum1, out + (base + ws + g + 8) * OO);
    }
}

extern "C" void kernel_launch(void* const* d_in, const int* in_sizes, int n_in,
                              void* d_out, int out_size) {
    const float* X = (const float*)d_in[0];
    const float* centers = (const float*)d_in[1];
    const float* sigmas = (const float*)d_in[2];
    const float* coeffs = (const float*)d_in[3];
    float* out = (float*)d_out;

    prep_kernel<<<4, 256>>>(centers, sigmas, coeffs);
    anfis_kernel<<<GRID, TPB>>>(X, out);
}